// round 12
// baseline (speedup 1.0000x reference)
#include <cuda_runtime.h>
#include <math.h>

#define Bq 8
#define Tq 2048
#define Dq 128
#define Kq 32
#define Nq 32
#define HNq 16
#define Mq 128
#define Lq 32
#define Cq 64            // Tq / Lq
#define ROWS (Bq*Tq)     // 16384 GEMM rows
#define KD2 1024         // GEMM inner dim after conjugate folding (32k * 32)

// ---------------- device scratch (static; no allocation at launch) ----------
__device__ float  g_xp[Bq][Kq][Tq];          // projected input [b][k][t]
__device__ float2 g_lam[Kq][Nq];
__device__ float2 g_lamL[Kq][Nq];
__device__ float2 g_Bp[Kq][Nq];
__device__ float  g_C[KD2][Mq];              // row k*32+j (j<16): Cr_j+Cr_{j+16}; row k*32+16+j: Ci_{j+16}-Ci_j
__device__ float  g_A[(size_t)ROWS * KD2];   // folded state matrix (67 MB)

#define FMA2(d, a, b) asm("fma.rn.f32x2 %0, %1, %2, %0;" : "+l"(d) : "l"(a), "l"(b))

// ---------------- K0: lambda/lamL/Bp (blocks 0..31) + folded C (blocks 32..) -
__global__ void k_precp(const float* __restrict__ theta,
                        const float* __restrict__ lnr,
                        const float* __restrict__ lni) {
    const int bx = blockIdx.x;
    if (bx < Kq) {
        if (threadIdx.x >= Nq) return;
        const int k = bx;
        const int j = threadIdx.x;
        __shared__ float th[HNq];
        if (j < HNq) th[j] = theta[k * HNq + j];
        __syncwarp(0xFFFFFFFF);

        const float phj = (j < HNq) ? th[j] : -th[j - HNq];
        g_lam[k][j] = make_float2(cosf(phj), sinf(phj));

        double aL  = (double)phj * 32.0;
        double red = aL - rint(aL * (0.5 / M_PI)) * (2.0 * M_PI);
        float  rf  = (float)red;
        g_lamL[k][j] = make_float2(cosf(rf), sinf(rf));

        // lnBp = -sum_{i != j} log(1 - e^{i(th_i - th_j)});
        // 1 - e^{id} = 2 sin(d/2) e^{i(d/2 - sgn(d) pi/2)}   (fp32 trig only)
        float  lr  = 0.0f;
        double liD = 0.0;
        #pragma unroll
        for (int i = 0; i < Nq; i++) {
            if (i == j) continue;
            float phi = (i < HNq) ? th[i] : -th[i - HNq];
            float d   = phi - phj;
            float s   = sinf(0.5f * d);
            lr  += logf(2.0f * fabsf(s));
            liD += (double)(0.5f * d) - copysign(0.5 * M_PI, (double)d);
        }
        double phiB = -liD;
        phiB -= rint(phiB * (0.5 / M_PI)) * (2.0 * M_PI);
        float mag = expf(-lr);
        float pb  = (float)phiB;
        g_Bp[k][j] = make_float2(mag * cosf(pb), mag * sinf(pb));
    } else {
        // folded C: one thread per (k, j<16, m); reads n=j and n=j+16
        int idx = (bx - Kq) * 256 + threadIdx.x;   // 0 .. 65535
        if (idx < Kq * HNq * Mq) {
            int k = idx >> 11;          // /(16*128)
            int j = (idx >> 7) & 15;
            int m = idx & 127;
            int i1 = (k * Nq + j) * Mq + m;
            int i2 = (k * Nq + j + HNq) * Mq + m;
            float r1 = expf(lnr[i1]), a1 = lni[i1];
            float r2 = expf(lnr[i2]), a2 = lni[i2];
            g_C[k * 32 + j][m]      = fmaf(r1, cosf(a1), r2 * cosf(a2));   // Cr_j + Cr_{j+16}
            g_C[k * 32 + 16 + j][m] = fmaf(r2, sinf(a2), -r1 * sinf(a1));  // Ci_{j+16} - Ci_j
        }
    }
}

// ---------------- K1: xp = x @ R, transposed to [b][k][t] --------------------
__global__ void k_xp(const float* __restrict__ x, const float* __restrict__ R) {
    __shared__ float xs[32][129];
    __shared__ float Rs[Dq][Kq];
    const int b  = blockIdx.y;
    const int t0 = blockIdx.x * 32;
    const int tid = threadIdx.x;

    for (int i = tid; i < Dq * Kq; i += 256) ((float*)Rs)[i] = R[i];
    for (int i = tid; i < 32 * Dq; i += 256) {
        int tl = i >> 7, d = i & 127;
        xs[tl][d] = x[((size_t)b * Tq + t0 + tl) * Dq + d];
    }
    __syncthreads();

    const int tl = tid & 31;
    const int k0 = tid >> 5;
    float acc[4] = {0.f, 0.f, 0.f, 0.f};
    for (int d = 0; d < Dq; d++) {
        float xv = xs[tl][d];
        #pragma unroll
        for (int j = 0; j < 4; j++) acc[j] = fmaf(xv, Rs[d][k0 + 8 * j], acc[j]);
    }
    #pragma unroll
    for (int j = 0; j < 4; j++) g_xp[b][k0 + 8 * j][t0 + tl] = acc[j];
}

// ---------------- K2: partials + cross-chunk scan + replay -> folded A -------
// lanes 16..31 compute the conjugate branch; their s.y = -si of partner lane.
__global__ __launch_bounds__(256) void k_states() {
    __shared__ float2 sP[Cq][Nq];
    __shared__ float2 sS[Cq][Nq];
    const int b = blockIdx.x >> 5;
    const int k = blockIdx.x & 31;
    const int lane = threadIdx.x & 31;
    const int w = threadIdx.x >> 5;

    const float2 lam = g_lam[k][lane];
    const float2 bp  = g_Bp[k][lane];

    for (int q = 0; q < 8; q++) {
        int c = w * 8 + q;
        const float* xp = &g_xp[b][k][c * Lq];
        float pr = 0.f, pi = 0.f;
        #pragma unroll
        for (int j = 0; j < Lq; j++) {
            float xv = xp[j];
            float nr = fmaf(lam.x, pr, fmaf(-lam.y, pi, bp.x * xv));
            float ni = fmaf(lam.y, pr, fmaf(lam.x, pi, bp.y * xv));
            pr = nr; pi = ni;
        }
        sP[c][lane] = make_float2(pr, pi);
    }
    __syncthreads();

    if (w == 0) {
        float2 lL = g_lamL[k][lane];
        float sr = 0.f, si = 0.f;
        for (int c = 0; c < Cq; c++) {
            sS[c][lane] = make_float2(sr, si);
            float2 p = sP[c][lane];
            float nr = fmaf(lL.x, sr, fmaf(-lL.y, si, p.x));
            float ni = fmaf(lL.y, sr, fmaf(lL.x, si, p.y));
            sr = nr; si = ni;
        }
    }
    __syncthreads();

    for (int q = 0; q < 8; q++) {
        int c = w * 8 + q;
        const float* xp = &g_xp[b][k][c * Lq];
        float2 s = sS[c][lane];
        size_t rb = ((size_t)b * Tq + c * Lq) * KD2 + k * 32;
        #pragma unroll
        for (int i = 0; i < Lq; i++) {
            // lane<16: sr_lane ; lane>=16: -s.y = si of (lane-16). One coalesced float per lane.
            g_A[rb + (size_t)i * KD2 + lane] = (lane < HNq) ? s.x : -s.y;
            float xv = xp[i];
            float nr = fmaf(lam.x, s.x, fmaf(-lam.y, s.y, bp.x * xv));
            float ni = fmaf(lam.y, s.x, fmaf(lam.x, s.y, bp.y * xv));
            s.x = nr; s.y = ni;
        }
    }
}

// ---------------- K3: SGEMM out = A[16384x1024] * C[1024x128] / 32 -----------
// 128 threads, block tile 64t x 64m, per-thread 8t x 4m.
// Accumulators packed over t-PAIRS: A read natural (no dup), C pre-duplicated.
#define MT 64
#define KT 16
#define NT2 (KD2 / KT)   // 64

__global__ __launch_bounds__(128, 5) void k_gemm(float* __restrict__ out) {
    __shared__ float  As[2][KT][68];    // natural floats, [kk][t]
    __shared__ float2 Cs[2][KT][66];    // duplicated (c,c), [kk][m]
    const int tid = threadIdx.x;
    const int tg = tid >> 4;            // 0..7  -> t rows tg*8..+7
    const int mg = tid & 15;            // 0..15 -> m cols mg*4..+3
    const size_t row0 = (size_t)blockIdx.x * MT;
    const int    cm0  = blockIdx.y * 64;           // m-half of C/out
    const float* Ab = g_A + row0 * KD2;

    const int ar = tid >> 1;            // 0..63 : A row
    const int ac = (tid & 1) * 8;       // 0/8   : kk offset
    const int cr = tid >> 3;            // 0..15 : C row (kk)
    const int cc = (tid & 7) * 8;       // C m offset within 64

    float4 av0, av1, cv0, cv1;
    av0 = *(const float4*)(Ab + (size_t)ar * KD2 + ac);
    av1 = *(const float4*)(Ab + (size_t)ar * KD2 + ac + 4);
    cv0 = *(const float4*)(&g_C[cr][cm0 + cc]);
    cv1 = *(const float4*)(&g_C[cr][cm0 + cc + 4]);
    As[0][ac + 0][ar] = av0.x;  As[0][ac + 1][ar] = av0.y;
    As[0][ac + 2][ar] = av0.z;  As[0][ac + 3][ar] = av0.w;
    As[0][ac + 4][ar] = av1.x;  As[0][ac + 5][ar] = av1.y;
    As[0][ac + 6][ar] = av1.z;  As[0][ac + 7][ar] = av1.w;
    Cs[0][cr][cc + 0] = make_float2(cv0.x, cv0.x);
    Cs[0][cr][cc + 1] = make_float2(cv0.y, cv0.y);
    Cs[0][cr][cc + 2] = make_float2(cv0.z, cv0.z);
    Cs[0][cr][cc + 3] = make_float2(cv0.w, cv0.w);
    Cs[0][cr][cc + 4] = make_float2(cv1.x, cv1.x);
    Cs[0][cr][cc + 5] = make_float2(cv1.y, cv1.y);
    Cs[0][cr][cc + 6] = make_float2(cv1.z, cv1.z);
    Cs[0][cr][cc + 7] = make_float2(cv1.w, cv1.w);
    __syncthreads();

    // acc[tp][m]: tp = t-pair (t0=2tp, t1=2tp+1), packed (s_t0*c, s_t1*c)
    unsigned long long acc[4][4];
    #pragma unroll
    for (int i = 0; i < 4; i++)
        #pragma unroll
        for (int p = 0; p < 4; p++) acc[i][p] = 0ull;

    for (int kt = 0; kt < NT2; kt++) {
        const int buf = kt & 1;
        if (kt + 1 < NT2) {
            int k0 = (kt + 1) * KT;
            av0 = *(const float4*)(Ab + (size_t)ar * KD2 + k0 + ac);
            av1 = *(const float4*)(Ab + (size_t)ar * KD2 + k0 + ac + 4);
            cv0 = *(const float4*)(&g_C[k0 + cr][cm0 + cc]);
            cv1 = *(const float4*)(&g_C[k0 + cr][cm0 + cc + 4]);
        }
        #pragma unroll
        for (int kk = 0; kk < KT; kk++) {
            // A: 8 natural floats = 2x LDS.128 -> 4 packed t-pairs
            ulonglong2 a03 = *(const ulonglong2*)&As[buf][kk][tg * 8];      // (t0,t1),(t2,t3)
            ulonglong2 a47 = *(const ulonglong2*)&As[buf][kk][tg * 8 + 4];  // (t4,t5),(t6,t7)
            // C: 4 duplicated pairs = 2x LDS.128
            ulonglong2 c01 = *(const ulonglong2*)&Cs[buf][kk][mg * 4];      // (c0,c0),(c1,c1)
            ulonglong2 c23 = *(const ulonglong2*)&Cs[buf][kk][mg * 4 + 2];  // (c2,c2),(c3,c3)
            FMA2(acc[0][0], a03.x, c01.x); FMA2(acc[0][1], a03.x, c01.y);
            FMA2(acc[0][2], a03.x, c23.x); FMA2(acc[0][3], a03.x, c23.y);
            FMA2(acc[1][0], a03.y, c01.x); FMA2(acc[1][1], a03.y, c01.y);
            FMA2(acc[1][2], a03.y, c23.x); FMA2(acc[1][3], a03.y, c23.y);
            FMA2(acc[2][0], a47.x, c01.x); FMA2(acc[2][1], a47.x, c01.y);
            FMA2(acc[2][2], a47.x, c23.x); FMA2(acc[2][3], a47.x, c23.y);
            FMA2(acc[3][0], a47.y, c01.x); FMA2(acc[3][1], a47.y, c01.y);
            FMA2(acc[3][2], a47.y, c23.x); FMA2(acc[3][3], a47.y, c23.y);
        }
        if (kt + 1 < NT2) {
            const int nb = buf ^ 1;
            As[nb][ac + 0][ar] = av0.x;  As[nb][ac + 1][ar] = av0.y;
            As[nb][ac + 2][ar] = av0.z;  As[nb][ac + 3][ar] = av0.w;
            As[nb][ac + 4][ar] = av1.x;  As[nb][ac + 5][ar] = av1.y;
            As[nb][ac + 6][ar] = av1.z;  As[nb][ac + 7][ar] = av1.w;
            Cs[nb][cr][cc + 0] = make_float2(cv0.x, cv0.x);
            Cs[nb][cr][cc + 1] = make_float2(cv0.y, cv0.y);
            Cs[nb][cr][cc + 2] = make_float2(cv0.z, cv0.z);
            Cs[nb][cr][cc + 3] = make_float2(cv0.w, cv0.w);
            Cs[nb][cr][cc + 4] = make_float2(cv1.x, cv1.x);
            Cs[nb][cr][cc + 5] = make_float2(cv1.y, cv1.y);
            Cs[nb][cr][cc + 6] = make_float2(cv1.z, cv1.z);
            Cs[nb][cr][cc + 7] = make_float2(cv1.w, cv1.w);
            __syncthreads();
        }
    }

    const float inv = 1.0f / 32.0f;
    #pragma unroll
    for (int tp = 0; tp < 4; tp++) {
        float2 m0 = *reinterpret_cast<float2*>(&acc[tp][0]);
        float2 m1 = *reinterpret_cast<float2*>(&acc[tp][1]);
        float2 m2 = *reinterpret_cast<float2*>(&acc[tp][2]);
        float2 m3 = *reinterpret_cast<float2*>(&acc[tp][3]);
        float* op0 = out + (row0 + tg * 8 + 2 * tp)     * Mq + cm0 + mg * 4;
        float* op1 = out + (row0 + tg * 8 + 2 * tp + 1) * Mq + cm0 + mg * 4;
        *(float4*)(op0) = make_float4(m0.x * inv, m1.x * inv, m2.x * inv, m3.x * inv);
        *(float4*)(op1) = make_float4(m0.y * inv, m1.y * inv, m2.y * inv, m3.y * inv);
    }
}

// ---------------- K4: out += xp @ D / 32 + Do --------------------------------
__global__ void k_dterm(const float* __restrict__ Dmat, const float* __restrict__ Dov,
                        float* __restrict__ out) {
    __shared__ float sxp[8][33];
    const int m   = threadIdx.x;
    const int bt0 = blockIdx.x * 8;
    for (int i = threadIdx.x; i < 8 * Kq; i += 128) {
        int r = i >> 5, k = i & 31;
        int bt = bt0 + r;
        sxp[r][k] = g_xp[bt >> 11][k][bt & 2047];
    }
    __syncthreads();
    float dov = Dov[m];
    for (int r = 0; r < 8; r++) {
        float acc = 0.f;
        #pragma unroll 8
        for (int k = 0; k < Kq; k++) acc = fmaf(sxp[r][k], Dmat[k * Mq + m], acc);
        size_t idx = (size_t)(bt0 + r) * Mq + m;
        out[idx] = out[idx] + fmaf(acc, 1.0f / 32.0f, dov);
    }
}

// ---------------- launch ------------------------------------------------------
extern "C" void kernel_launch(void* const* d_in, const int* in_sizes, int n_in,
                              void* d_out, int out_size) {
    const float* x     = (const float*)d_in[0];
    const float* R     = (const float*)d_in[1];
    const float* theta = (const float*)d_in[2];
    const float* lnC_r = (const float*)d_in[3];
    const float* lnC_i = (const float*)d_in[4];
    const float* Dmat  = (const float*)d_in[5];
    const float* Dov   = (const float*)d_in[6];
    float* out = (float*)d_out;

    k_precp<<<Kq + (Kq * HNq * Mq + 255) / 256, 256>>>(theta, lnC_r, lnC_i);   // 0
    k_xp<<<dim3(Tq / 32, Bq), 256>>>(x, R);                                    // 1
    k_states<<<Bq * Kq, 256>>>();                                              // 2
    k_gemm<<<dim3(ROWS / MT, 2), 128>>>(out);                                  // 3
    k_dterm<<<(Bq * Tq) / 8, 128>>>(Dmat, Dov, out);                           // 4
}

// round 15
// speedup vs baseline: 1.6206x; 1.6206x over previous
#include <cuda_runtime.h>
#include <math.h>
#include <stdint.h>

#define Bq 8
#define Tq 2048
#define Dq 128
#define Kq 32
#define Nq 32
#define HNq 16
#define Mq 128
#define Lq 32
#define Cq 64            // Tq / Lq
#define ROWS (Bq*Tq)     // 16384 GEMM rows
#define KD2 1024         // GEMM inner dim after conjugate folding
#define KT 16            // K-chunk
#define NKT (KD2/KT)     // 64 chunks

// ---------------- device scratch (static; no allocation at launch) ----------
__device__ float    g_xp[Bq][Kq][Tq];
__device__ float2   g_lam[Kq][Nq];
__device__ float2   g_lamL[Kq][Nq];
__device__ float2   g_Bp[Kq][Nq];
__device__ float    g_A[(size_t)ROWS * KD2];   // folded state matrix fp32 (67 MB)
__device__ uint32_t g_C1[KD2][Mq];             // tf32 split hi of folded C * (1/32)
__device__ uint32_t g_C2[KD2][Mq];             // tf32 split lo

__device__ __forceinline__ uint32_t f2tf(float x) {
    uint32_t r; asm("cvt.rna.tf32.f32 %0, %1;" : "=r"(r) : "f"(x)); return r;
}
__device__ __forceinline__ void mma_tf32(float* d, const uint32_t* a, const uint32_t* b) {
    asm volatile(
        "mma.sync.aligned.m16n8k8.row.col.f32.tf32.tf32.f32 "
        "{%0,%1,%2,%3}, {%4,%5,%6,%7}, {%8,%9}, {%0,%1,%2,%3};"
        : "+f"(d[0]), "+f"(d[1]), "+f"(d[2]), "+f"(d[3])
        : "r"(a[0]), "r"(a[1]), "r"(a[2]), "r"(a[3]), "r"(b[0]), "r"(b[1]));
}

// ---------------- K0: lambda/lamL/Bp (blocks 0..31) + split C (blocks 32..) --
__global__ void k_precp(const float* __restrict__ theta,
                        const float* __restrict__ lnr,
                        const float* __restrict__ lni) {
    const int bx = blockIdx.x;
    if (bx < Kq) {
        if (threadIdx.x >= Nq) return;
        const int k = bx;
        const int j = threadIdx.x;
        __shared__ float th[HNq];
        if (j < HNq) th[j] = theta[k * HNq + j];
        __syncwarp(0xFFFFFFFF);

        const float phj = (j < HNq) ? th[j] : -th[j - HNq];
        g_lam[k][j] = make_float2(cosf(phj), sinf(phj));

        double aL  = (double)phj * 32.0;
        double red = aL - rint(aL * (0.5 / M_PI)) * (2.0 * M_PI);
        float  rf  = (float)red;
        g_lamL[k][j] = make_float2(cosf(rf), sinf(rf));

        // lnBp = -sum_{i != j} log(1 - e^{i(th_i - th_j)}); fp32 trig only
        float  lr  = 0.0f;
        double liD = 0.0;
        #pragma unroll
        for (int i = 0; i < Nq; i++) {
            if (i == j) continue;
            float phi = (i < HNq) ? th[i] : -th[i - HNq];
            float d   = phi - phj;
            float s   = sinf(0.5f * d);
            lr  += logf(2.0f * fabsf(s));
            liD += (double)(0.5f * d) - copysign(0.5 * M_PI, (double)d);
        }
        double phiB = -liD;
        phiB -= rint(phiB * (0.5 / M_PI)) * (2.0 * M_PI);
        float mag = expf(-lr);
        float pb  = (float)phiB;
        g_Bp[k][j] = make_float2(mag * cosf(pb), mag * sinf(pb));
    } else {
        // folded C rows: k*32+j -> Cr_j + Cr_{j+16};  k*32+16+j -> Ci_{j+16} - Ci_j
        // scaled by 1/32 (mean over k), then 2-way tf32 split.
        int idx = (bx - Kq) * 256 + threadIdx.x;   // over K*HN*M = 65536
        if (idx < Kq * HNq * Mq) {
            int k = idx >> 11;
            int j = (idx >> 7) & 15;
            int m = idx & 127;
            int i1 = (k * Nq + j) * Mq + m;
            int i2 = (k * Nq + j + HNq) * Mq + m;
            float r1 = expf(lnr[i1]), a1 = lni[i1];
            float r2 = expf(lnr[i2]), a2 = lni[i2];
            float v1 = fmaf(r1, cosf(a1), r2 * cosf(a2)) * (1.0f / 32.0f);
            float v2 = fmaf(r2, sinf(a2), -r1 * sinf(a1)) * (1.0f / 32.0f);
            int row1 = k * 32 + j;
            int row2 = k * 32 + 16 + j;
            uint32_t h1 = f2tf(v1);
            g_C1[row1][m] = h1;
            g_C2[row1][m] = f2tf(v1 - __uint_as_float(h1));
            uint32_t h2 = f2tf(v2);
            g_C1[row2][m] = h2;
            g_C2[row2][m] = f2tf(v2 - __uint_as_float(h2));
        }
    }
}

// ---------------- K1: xp = x @ R, transposed to [b][k][t] --------------------
__global__ void k_xp(const float* __restrict__ x, const float* __restrict__ R) {
    __shared__ float xs[32][129];
    __shared__ float Rs[Dq][Kq];
    const int b  = blockIdx.y;
    const int t0 = blockIdx.x * 32;
    const int tid = threadIdx.x;

    for (int i = tid; i < Dq * Kq; i += 256) ((float*)Rs)[i] = R[i];
    for (int i = tid; i < 32 * Dq; i += 256) {
        int tl = i >> 7, d = i & 127;
        xs[tl][d] = x[((size_t)b * Tq + t0 + tl) * Dq + d];
    }
    __syncthreads();

    const int tl = tid & 31;
    const int k0 = tid >> 5;
    float acc[4] = {0.f, 0.f, 0.f, 0.f};
    for (int d = 0; d < Dq; d++) {
        float xv = xs[tl][d];
        #pragma unroll
        for (int j = 0; j < 4; j++) acc[j] = fmaf(xv, Rs[d][k0 + 8 * j], acc[j]);
    }
    #pragma unroll
    for (int j = 0; j < 4; j++) g_xp[b][k0 + 8 * j][t0 + tl] = acc[j];
}

// ---------------- K2: partials + cross-chunk scan + replay -> folded A -------
__global__ __launch_bounds__(256) void k_states() {
    __shared__ float2 sP[Cq][Nq];
    __shared__ float2 sS[Cq][Nq];
    const int b = blockIdx.x >> 5;
    const int k = blockIdx.x & 31;
    const int lane = threadIdx.x & 31;
    const int w = threadIdx.x >> 5;

    const float2 lam = g_lam[k][lane];
    const float2 bp  = g_Bp[k][lane];

    for (int q = 0; q < 8; q++) {
        int c = w * 8 + q;
        const float* xp = &g_xp[b][k][c * Lq];
        float pr = 0.f, pi = 0.f;
        #pragma unroll
        for (int j = 0; j < Lq; j++) {
            float xv = xp[j];
            float nr = fmaf(lam.x, pr, fmaf(-lam.y, pi, bp.x * xv));
            float ni = fmaf(lam.y, pr, fmaf(lam.x, pi, bp.y * xv));
            pr = nr; pi = ni;
        }
        sP[c][lane] = make_float2(pr, pi);
    }
    __syncthreads();

    if (w == 0) {
        float2 lL = g_lamL[k][lane];
        float sr = 0.f, si = 0.f;
        for (int c = 0; c < Cq; c++) {
            sS[c][lane] = make_float2(sr, si);
            float2 p = sP[c][lane];
            float nr = fmaf(lL.x, sr, fmaf(-lL.y, si, p.x));
            float ni = fmaf(lL.y, sr, fmaf(lL.x, si, p.y));
            sr = nr; si = ni;
        }
    }
    __syncthreads();

    for (int q = 0; q < 8; q++) {
        int c = w * 8 + q;
        const float* xp = &g_xp[b][k][c * Lq];
        float2 s = sS[c][lane];
        size_t rb = ((size_t)b * Tq + c * Lq) * KD2 + k * 32;
        #pragma unroll
        for (int i = 0; i < Lq; i++) {
            g_A[rb + (size_t)i * KD2 + lane] = (lane < HNq) ? s.x : -s.y;
            float xv = xp[i];
            float nr = fmaf(lam.x, s.x, fmaf(-lam.y, s.y, bp.x * xv));
            float ni = fmaf(lam.y, s.x, fmaf(lam.x, s.y, bp.y * xv));
            s.x = nr; s.y = ni;
        }
    }
}

// ---------------- K3: tf32 mma.sync GEMM: out = A[16384x1024] * Csplit -------
// 128 CTAs x 256 thr; CTA tile 128 rows x 128 cols; warp w: rows w*16..+15.
// Terms: a1*b1 + a1*b2 + a2*b1  (2-way tf32 split, A split at frag-load time).
__global__ __launch_bounds__(256) void k_gemm(float* __restrict__ out) {
    __shared__ float    As[KT][132];
    __shared__ uint32_t Bs1[KT][132];
    __shared__ uint32_t Bs2[KT][132];
    const int tid  = threadIdx.x;
    const int w    = tid >> 5;
    const int lane = tid & 31;
    const int g    = lane >> 2;          // group 0..7
    const int t4   = lane & 3;           // thread-in-group
    const int row0 = blockIdx.x * 128;

    // prefetch mapping
    const int pr = tid >> 1;             // A row 0..127
    const int pk = (tid & 1) * 8;        // A k sub-offset
    const int bk = tid >> 4;             // B k row 0..15
    const int bm = (tid & 15) * 8;       // B m offset

    const float* Ab = g_A + (size_t)(row0 + pr) * KD2 + pk;

    float acc[16][4];
    #pragma unroll
    for (int nt = 0; nt < 16; nt++)
        #pragma unroll
        for (int q = 0; q < 4; q++) acc[nt][q] = 0.f;

    // chunk 0 prefetch
    float4 av0 = *(const float4*)(Ab);
    float4 av1 = *(const float4*)(Ab + 4);
    uint4  b10 = *(const uint4*)(&g_C1[bk][bm]);
    uint4  b11 = *(const uint4*)(&g_C1[bk][bm + 4]);
    uint4  b20 = *(const uint4*)(&g_C2[bk][bm]);
    uint4  b21 = *(const uint4*)(&g_C2[bk][bm + 4]);

    for (int kt = 0; kt < NKT; kt++) {
        // store prefetched chunk into smem
        As[pk + 0][pr] = av0.x;  As[pk + 1][pr] = av0.y;
        As[pk + 2][pr] = av0.z;  As[pk + 3][pr] = av0.w;
        As[pk + 4][pr] = av1.x;  As[pk + 5][pr] = av1.y;
        As[pk + 6][pr] = av1.z;  As[pk + 7][pr] = av1.w;
        *(uint4*)(&Bs1[bk][bm])     = b10;
        *(uint4*)(&Bs1[bk][bm + 4]) = b11;
        *(uint4*)(&Bs2[bk][bm])     = b20;
        *(uint4*)(&Bs2[bk][bm + 4]) = b21;
        __syncthreads();

        if (kt + 1 < NKT) {
            int kg = (kt + 1) * KT;
            av0 = *(const float4*)(Ab + kg);
            av1 = *(const float4*)(Ab + kg + 4);
            b10 = *(const uint4*)(&g_C1[kg + bk][bm]);
            b11 = *(const uint4*)(&g_C1[kg + bk][bm + 4]);
            b20 = *(const uint4*)(&g_C2[kg + bk][bm]);
            b21 = *(const uint4*)(&g_C2[kg + bk][bm + 4]);
        }

        #pragma unroll
        for (int ks = 0; ks < 2; ks++) {
            const int k0 = ks * 8;
            uint32_t A1[4], A2[4];
            #pragma unroll
            for (int q = 0; q < 4; q++) {
                int kk = k0 + t4 + ((q >= 2) ? 4 : 0);
                int rr = w * 16 + g + ((q & 1) ? 8 : 0);
                float a = As[kk][rr];
                uint32_t u = f2tf(a);
                A1[q] = u;
                A2[q] = f2tf(a - __uint_as_float(u));
            }
            #pragma unroll
            for (int nt = 0; nt < 16; nt++) {
                const int nn = nt * 8 + g;
                uint32_t B1f[2], B2f[2];
                B1f[0] = Bs1[k0 + t4][nn];
                B1f[1] = Bs1[k0 + t4 + 4][nn];
                B2f[0] = Bs2[k0 + t4][nn];
                B2f[1] = Bs2[k0 + t4 + 4][nn];
                mma_tf32(acc[nt], A1, B1f);
                mma_tf32(acc[nt], A1, B2f);
                mma_tf32(acc[nt], A2, B1f);
            }
        }
        __syncthreads();
    }

    // epilogue (1/32 already folded into C)
    #pragma unroll
    for (int nt = 0; nt < 16; nt++) {
        int col = nt * 8 + t4 * 2;
        float* o0 = out + (size_t)(row0 + w * 16 + g) * Mq + col;
        float* o1 = out + (size_t)(row0 + w * 16 + g + 8) * Mq + col;
        *(float2*)o0 = make_float2(acc[nt][0], acc[nt][1]);
        *(float2*)o1 = make_float2(acc[nt][2], acc[nt][3]);
    }
}

// ---------------- K4: out += xp @ D / 32 + Do --------------------------------
__global__ void k_dterm(const float* __restrict__ Dmat, const float* __restrict__ Dov,
                        float* __restrict__ out) {
    __shared__ float sxp[8][33];
    const int m   = threadIdx.x;
    const int bt0 = blockIdx.x * 8;
    for (int i = threadIdx.x; i < 8 * Kq; i += 128) {
        int r = i >> 5, k = i & 31;
        int bt = bt0 + r;
        sxp[r][k] = g_xp[bt >> 11][k][bt & 2047];
    }
    __syncthreads();
    float dov = Dov[m];
    for (int r = 0; r < 8; r++) {
        float acc = 0.f;
        #pragma unroll 8
        for (int k = 0; k < Kq; k++) acc = fmaf(sxp[r][k], Dmat[k * Mq + m], acc);
        size_t idx = (size_t)(bt0 + r) * Mq + m;
        out[idx] = out[idx] + fmaf(acc, 1.0f / 32.0f, dov);
    }
}

// ---------------- launch ------------------------------------------------------
extern "C" void kernel_launch(void* const* d_in, const int* in_sizes, int n_in,
                              void* d_out, int out_size) {
    const float* x     = (const float*)d_in[0];
    const float* R     = (const float*)d_in[1];
    const float* theta = (const float*)d_in[2];
    const float* lnC_r = (const float*)d_in[3];
    const float* lnC_i = (const float*)d_in[4];
    const float* Dmat  = (const float*)d_in[5];
    const float* Dov   = (const float*)d_in[6];
    float* out = (float*)d_out;

    k_precp<<<Kq + (Kq * HNq * Mq + 255) / 256, 256>>>(theta, lnC_r, lnC_i);   // 0
    k_xp<<<dim3(Tq / 32, Bq), 256>>>(x, R);                                    // 1
    k_states<<<Bq * Kq, 256>>>();                                              // 2
    k_gemm<<<ROWS / 128, 256>>>(out);                                          // 3
    k_dterm<<<(Bq * Tq) / 8, 128>>>(Dmat, Dov, out);                           // 4
}

// round 17
// speedup vs baseline: 1.7668x; 1.0902x over previous
#include <cuda_runtime.h>
#include <math.h>
#include <stdint.h>

#define Bq 8
#define Tq 2048
#define Dq 128
#define Kq 32
#define Nq 32
#define HNq 16
#define Mq 128
#define Lq 32
#define Cq 64            // Tq / Lq
#define ROWS (Bq*Tq)     // 16384 GEMM rows
#define KD2 1024         // GEMM inner dim after conjugate folding
#define KT 16            // K-chunk
#define NKT (KD2/KT)     // 64 chunks

// ---------------- device scratch (static; no allocation at launch) ----------
__device__ float    g_xp[Bq][Kq][Tq];
__device__ float2   g_lam[Kq][Nq];
__device__ float2   g_lamL[Kq][Nq];
__device__ float2   g_Bp[Kq][Nq];
__device__ float    g_A[(size_t)ROWS * KD2];   // folded state matrix fp32 (67 MB)
__device__ uint32_t g_C1[KD2][Mq];             // tf32 split hi of folded C * (1/32)
__device__ uint32_t g_C2[KD2][Mq];             // tf32 split lo

__device__ __forceinline__ uint32_t f2tf(float x) {
    uint32_t r; asm("cvt.rna.tf32.f32 %0, %1;" : "=r"(r) : "f"(x)); return r;
}
__device__ __forceinline__ void mma_tf32(float* d, const uint32_t* a, const uint32_t* b) {
    asm volatile(
        "mma.sync.aligned.m16n8k8.row.col.f32.tf32.tf32.f32 "
        "{%0,%1,%2,%3}, {%4,%5,%6,%7}, {%8,%9}, {%0,%1,%2,%3};"
        : "+f"(d[0]), "+f"(d[1]), "+f"(d[2]), "+f"(d[3])
        : "r"(a[0]), "r"(a[1]), "r"(a[2]), "r"(a[3]), "r"(b[0]), "r"(b[1]));
}

// ---------------- K0: lambda/lamL/Bp (blocks 0..31) + split C (blocks 32..) --
__global__ void k_precp(const float* __restrict__ theta,
                        const float* __restrict__ lnr,
                        const float* __restrict__ lni) {
    const int bx = blockIdx.x;
    if (bx < Kq) {
        if (threadIdx.x >= Nq) return;
        const int k = bx;
        const int j = threadIdx.x;
        __shared__ float th[HNq];
        if (j < HNq) th[j] = theta[k * HNq + j];
        __syncwarp(0xFFFFFFFF);

        const float phj = (j < HNq) ? th[j] : -th[j - HNq];
        g_lam[k][j] = make_float2(cosf(phj), sinf(phj));

        double aL  = (double)phj * 32.0;
        double red = aL - rint(aL * (0.5 / M_PI)) * (2.0 * M_PI);
        float  rf  = (float)red;
        g_lamL[k][j] = make_float2(cosf(rf), sinf(rf));

        // lnBp = -sum_{i != j} log(1 - e^{i(th_i - th_j)}); fp32 trig only
        float  lr  = 0.0f;
        double liD = 0.0;
        #pragma unroll
        for (int i = 0; i < Nq; i++) {
            if (i == j) continue;
            float phi = (i < HNq) ? th[i] : -th[i - HNq];
            float d   = phi - phj;
            float s   = sinf(0.5f * d);
            lr  += logf(2.0f * fabsf(s));
            liD += (double)(0.5f * d) - copysign(0.5 * M_PI, (double)d);
        }
        double phiB = -liD;
        phiB -= rint(phiB * (0.5 / M_PI)) * (2.0 * M_PI);
        float mag = expf(-lr);
        float pb  = (float)phiB;
        g_Bp[k][j] = make_float2(mag * cosf(pb), mag * sinf(pb));
    } else {
        // folded C rows: k*32+j -> Cr_j + Cr_{j+16};  k*32+16+j -> Ci_{j+16} - Ci_j
        // scaled by 1/32 (mean over k), then 2-way tf32 split.
        int idx = (bx - Kq) * 256 + threadIdx.x;   // over K*HN*M = 65536
        if (idx < Kq * HNq * Mq) {
            int k = idx >> 11;
            int j = (idx >> 7) & 15;
            int m = idx & 127;
            int i1 = (k * Nq + j) * Mq + m;
            int i2 = (k * Nq + j + HNq) * Mq + m;
            float r1 = expf(lnr[i1]), a1 = lni[i1];
            float r2 = expf(lnr[i2]), a2 = lni[i2];
            float v1 = fmaf(r1, cosf(a1), r2 * cosf(a2)) * (1.0f / 32.0f);
            float v2 = fmaf(r2, sinf(a2), -r1 * sinf(a1)) * (1.0f / 32.0f);
            int row1 = k * 32 + j;
            int row2 = k * 32 + 16 + j;
            uint32_t h1 = f2tf(v1);
            g_C1[row1][m] = h1;
            g_C2[row1][m] = f2tf(v1 - __uint_as_float(h1));
            uint32_t h2 = f2tf(v2);
            g_C1[row2][m] = h2;
            g_C2[row2][m] = f2tf(v2 - __uint_as_float(h2));
        }
    }
}

// ---------------- K1: xp = x @ R, transposed to [b][k][t] --------------------
__global__ void k_xp(const float* __restrict__ x, const float* __restrict__ R) {
    __shared__ float xs[32][129];
    __shared__ float Rs[Dq][Kq];
    const int b  = blockIdx.y;
    const int t0 = blockIdx.x * 32;
    const int tid = threadIdx.x;

    for (int i = tid; i < Dq * Kq; i += 256) ((float*)Rs)[i] = R[i];
    for (int i = tid; i < 32 * Dq; i += 256) {
        int tl = i >> 7, d = i & 127;
        xs[tl][d] = x[((size_t)b * Tq + t0 + tl) * Dq + d];
    }
    __syncthreads();

    const int tl = tid & 31;
    const int k0 = tid >> 5;
    float acc[4] = {0.f, 0.f, 0.f, 0.f};
    for (int d = 0; d < Dq; d++) {
        float xv = xs[tl][d];
        #pragma unroll
        for (int j = 0; j < 4; j++) acc[j] = fmaf(xv, Rs[d][k0 + 8 * j], acc[j]);
    }
    #pragma unroll
    for (int j = 0; j < 4; j++) g_xp[b][k0 + 8 * j][t0 + tl] = acc[j];
}

// ---------------- K2: partials + cross-chunk scan + replay -> folded A -------
__global__ __launch_bounds__(256) void k_states() {
    __shared__ float2 sP[Cq][Nq];
    __shared__ float2 sS[Cq][Nq];
    const int b = blockIdx.x >> 5;
    const int k = blockIdx.x & 31;
    const int lane = threadIdx.x & 31;
    const int w = threadIdx.x >> 5;

    const float2 lam = g_lam[k][lane];
    const float2 bp  = g_Bp[k][lane];

    for (int q = 0; q < 8; q++) {
        int c = w * 8 + q;
        const float* xp = &g_xp[b][k][c * Lq];
        float pr = 0.f, pi = 0.f;
        #pragma unroll
        for (int j = 0; j < Lq; j++) {
            float xv = xp[j];
            float nr = fmaf(lam.x, pr, fmaf(-lam.y, pi, bp.x * xv));
            float ni = fmaf(lam.y, pr, fmaf(lam.x, pi, bp.y * xv));
            pr = nr; pi = ni;
        }
        sP[c][lane] = make_float2(pr, pi);
    }
    __syncthreads();

    if (w == 0) {
        float2 lL = g_lamL[k][lane];
        float sr = 0.f, si = 0.f;
        for (int c = 0; c < Cq; c++) {
            sS[c][lane] = make_float2(sr, si);
            float2 p = sP[c][lane];
            float nr = fmaf(lL.x, sr, fmaf(-lL.y, si, p.x));
            float ni = fmaf(lL.y, sr, fmaf(lL.x, si, p.y));
            sr = nr; si = ni;
        }
    }
    __syncthreads();

    for (int q = 0; q < 8; q++) {
        int c = w * 8 + q;
        const float* xp = &g_xp[b][k][c * Lq];
        float2 s = sS[c][lane];
        size_t rb = ((size_t)b * Tq + c * Lq) * KD2 + k * 32;
        #pragma unroll
        for (int i = 0; i < Lq; i++) {
            g_A[rb + (size_t)i * KD2 + lane] = (lane < HNq) ? s.x : -s.y;
            float xv = xp[i];
            float nr = fmaf(lam.x, s.x, fmaf(-lam.y, s.y, bp.x * xv));
            float ni = fmaf(lam.y, s.x, fmaf(lam.x, s.y, bp.y * xv));
            s.x = nr; s.y = ni;
        }
    }
}

// ---------------- K3: tf32 mma.sync GEMM: out = A[16384x1024] * Csplit -------
// 256 CTAs x 256 thr, 2 CTAs/SM. CTA tile 64 rows x 128 cols.
// Warp grid 2x4: warp tile 32 rows x 32 cols -> B fragments reused over 2 row-tiles.
// Conflict-free smem: A row-major stride 20, B k-major stride 136.
__global__ __launch_bounds__(256, 2) void k_gemm(float* __restrict__ out) {
    __shared__ float    As[64][20];       // [row][k]
    __shared__ uint32_t Bs1[KT][136];
    __shared__ uint32_t Bs2[KT][136];
    const int tid  = threadIdx.x;
    const int w    = tid >> 5;
    const int lane = tid & 31;
    const int g    = lane >> 2;          // 0..7
    const int t4   = lane & 3;           // 0..3
    const int wr   = (w & 1) * 32;       // warp row offset
    const int wc   = (w >> 1) * 32;      // warp col offset
    const int row0 = blockIdx.x * 64;

    // fill mapping
    const int apr = tid >> 2;            // A row 0..63
    const int apk = (tid & 3) * 4;       // A k quad
    const int bk  = tid >> 4;            // B k row 0..15
    const int bm  = (tid & 15) * 8;      // B m offset (8 words)

    const float* Ab = g_A + (size_t)(row0 + apr) * KD2 + apk;

    float acc[2][4][4];
    #pragma unroll
    for (int rt = 0; rt < 2; rt++)
        #pragma unroll
        for (int nt = 0; nt < 4; nt++)
            #pragma unroll
            for (int q = 0; q < 4; q++) acc[rt][nt][q] = 0.f;

    // chunk 0 prefetch
    float4 av  = *(const float4*)(Ab);
    uint4  b10 = *(const uint4*)(&g_C1[bk][bm]);
    uint4  b11 = *(const uint4*)(&g_C1[bk][bm + 4]);
    uint4  b20 = *(const uint4*)(&g_C2[bk][bm]);
    uint4  b21 = *(const uint4*)(&g_C2[bk][bm + 4]);

    for (int kt = 0; kt < NKT; kt++) {
        *(float4*)(&As[apr][apk]) = av;
        *(uint4*)(&Bs1[bk][bm])     = b10;
        *(uint4*)(&Bs1[bk][bm + 4]) = b11;
        *(uint4*)(&Bs2[bk][bm])     = b20;
        *(uint4*)(&Bs2[bk][bm + 4]) = b21;
        __syncthreads();

        if (kt + 1 < NKT) {
            int kg = (kt + 1) * KT;
            av  = *(const float4*)(Ab + kg);
            b10 = *(const uint4*)(&g_C1[kg + bk][bm]);
            b11 = *(const uint4*)(&g_C1[kg + bk][bm + 4]);
            b20 = *(const uint4*)(&g_C2[kg + bk][bm]);
            b21 = *(const uint4*)(&g_C2[kg + bk][bm + 4]);
        }

        #pragma unroll
        for (int ks = 0; ks < 2; ks++) {
            const int k0 = ks * 8;
            // A fragments for both 16-row tiles, split into tf32 hi/lo
            uint32_t A1[2][4], A2[2][4];
            #pragma unroll
            for (int rt = 0; rt < 2; rt++) {
                #pragma unroll
                for (int q = 0; q < 4; q++) {
                    int rr = wr + rt * 16 + g + ((q & 1) ? 8 : 0);
                    int kk = k0 + t4 + ((q >= 2) ? 4 : 0);
                    float a = As[rr][kk];
                    uint32_t u = f2tf(a);
                    A1[rt][q] = u;
                    A2[rt][q] = f2tf(a - __uint_as_float(u));
                }
            }
            #pragma unroll
            for (int nt = 0; nt < 4; nt++) {
                const int nn = wc + nt * 8 + g;
                uint32_t B1f[2], B2f[2];
                B1f[0] = Bs1[k0 + t4][nn];
                B1f[1] = Bs1[k0 + t4 + 4][nn];
                B2f[0] = Bs2[k0 + t4][nn];
                B2f[1] = Bs2[k0 + t4 + 4][nn];
                #pragma unroll
                for (int rt = 0; rt < 2; rt++) {
                    mma_tf32(acc[rt][nt], A1[rt], B1f);
                    mma_tf32(acc[rt][nt], A1[rt], B2f);
                    mma_tf32(acc[rt][nt], A2[rt], B1f);
                }
            }
        }
        __syncthreads();
    }

    // epilogue (1/32 already folded into C)
    #pragma unroll
    for (int rt = 0; rt < 2; rt++) {
        #pragma unroll
        for (int nt = 0; nt < 4; nt++) {
            int row = row0 + wr + rt * 16 + g;
            int col = wc + nt * 8 + t4 * 2;
            float* o0 = out + (size_t)row * Mq + col;
            float* o1 = out + (size_t)(row + 8) * Mq + col;
            *(float2*)o0 = make_float2(acc[rt][nt][0], acc[rt][nt][1]);
            *(float2*)o1 = make_float2(acc[rt][nt][2], acc[rt][nt][3]);
        }
    }
}

// ---------------- K4: out += xp @ D / 32 + Do --------------------------------
__global__ void k_dterm(const float* __restrict__ Dmat, const float* __restrict__ Dov,
                        float* __restrict__ out) {
    __shared__ float sxp[8][33];
    const int m   = threadIdx.x;
    const int bt0 = blockIdx.x * 8;
    for (int i = threadIdx.x; i < 8 * Kq; i += 128) {
        int r = i >> 5, k = i & 31;
        int bt = bt0 + r;
        sxp[r][k] = g_xp[bt >> 11][k][bt & 2047];
    }
    __syncthreads();
    float dov = Dov[m];
    for (int r = 0; r < 8; r++) {
        float acc = 0.f;
        #pragma unroll 8
        for (int k = 0; k < Kq; k++) acc = fmaf(sxp[r][k], Dmat[k * Mq + m], acc);
        size_t idx = (size_t)(bt0 + r) * Mq + m;
        out[idx] = out[idx] + fmaf(acc, 1.0f / 32.0f, dov);
    }
}

// ---------------- launch ------------------------------------------------------
extern "C" void kernel_launch(void* const* d_in, const int* in_sizes, int n_in,
                              void* d_out, int out_size) {
    const float* x     = (const float*)d_in[0];
    const float* R     = (const float*)d_in[1];
    const float* theta = (const float*)d_in[2];
    const float* lnC_r = (const float*)d_in[3];
    const float* lnC_i = (const float*)d_in[4];
    const float* Dmat  = (const float*)d_in[5];
    const float* Dov   = (const float*)d_in[6];
    float* out = (float*)d_out;

    k_precp<<<Kq + (Kq * HNq * Mq + 255) / 256, 256>>>(theta, lnC_r, lnC_i);   // 0
    k_xp<<<dim3(Tq / 32, Bq), 256>>>(x, R);                                    // 1
    k_states<<<Bq * Kq, 256>>>();                                              // 2
    k_gemm<<<ROWS / 64, 256>>>(out);                                           // 3
    k_dterm<<<(Bq * Tq) / 8, 128>>>(Dmat, Dov, out);                           // 4
}